// round 2
// baseline (speedup 1.0000x reference)
#include <cuda_runtime.h>

#define NTOK 32768
#define NH 32
#define NC 27  // float4 chunks per token: Q=0..8, K=9..17, V=18..26 (each section 34 padded to 36)

// Scratch: 10 obs slices (pred reuses slice 0). 10*27*32768*16B = 141.6 MB
__device__ float4 g_scratch[10 * NC * NTOK];

// ---------------------------------------------------------------------------
// Kernel 1: per-token QKV projection.
//   f = [h(n, 0:32), row/64, col/64, 0, 0]  (36 floats, padded)
//   chunk c: section sec=c/9 (0=Q,1=K,2=V), within-offset ww=4*(c%9);
//   outputs = ipw[sec*34 + ww + j, :] @ f + ipb   (j=0..3, pad -> 0 for ww+j>=34)
// Scratch layout: g_scratch[z*NC*NTOK + c*NTOK + n]  -> coalesced.
// ---------------------------------------------------------------------------
__global__ void __launch_bounds__(256) qkv_kernel(
    const float* __restrict__ hbase,   // (z, NTOK, 32)
    const float* __restrict__ ipw,     // (102, 34)
    const float* __restrict__ ipb)     // (102)
{
    __shared__ float4 sw[36 * NC];     // sw[i*NC + c] = weights for chunk c, input feature i
    __shared__ float4 sb[NC];

    int tid = threadIdx.x;
    for (int idx = tid; idx < 36 * NC; idx += 256) {
        int i = idx / NC, c = idx % NC;
        int sec = c / 9, ww = 4 * (c % 9);
        float4 v;
        v.x = (i < 34 && ww + 0 < 34) ? ipw[(sec * 34 + ww + 0) * 34 + i] : 0.f;
        v.y = (i < 34 && ww + 1 < 34) ? ipw[(sec * 34 + ww + 1) * 34 + i] : 0.f;
        v.z = (i < 34 && ww + 2 < 34) ? ipw[(sec * 34 + ww + 2) * 34 + i] : 0.f;
        v.w = (i < 34 && ww + 3 < 34) ? ipw[(sec * 34 + ww + 3) * 34 + i] : 0.f;
        sw[idx] = v;
    }
    if (tid < NC) {
        int sec = tid / 9, ww = 4 * (tid % 9);
        float4 v;
        v.x = (ww + 0 < 34) ? ipb[sec * 34 + ww + 0] : 0.f;
        v.y = (ww + 1 < 34) ? ipb[sec * 34 + ww + 1] : 0.f;
        v.z = (ww + 2 < 34) ? ipb[sec * 34 + ww + 2] : 0.f;
        v.w = (ww + 3 < 34) ? ipb[sec * 34 + ww + 3] : 0.f;
        sb[tid] = v;
    }
    __syncthreads();

    int n = blockIdx.x * 256 + tid;
    const float* hrow = hbase + ((size_t)blockIdx.z * NTOK + n) * NH;
    const float4* h4 = reinterpret_cast<const float4*>(hrow);

    float f[36];
#pragma unroll
    for (int i = 0; i < 8; i++) {
        float4 v = h4[i];
        f[4 * i + 0] = v.x; f[4 * i + 1] = v.y;
        f[4 * i + 2] = v.z; f[4 * i + 3] = v.w;
    }
    int p = n & 4095;
    f[32] = (float)(p >> 6) * (1.f / 64.f);
    f[33] = (float)(p & 63) * (1.f / 64.f);
    f[34] = 0.f; f[35] = 0.f;

    float4* outp = g_scratch + (size_t)blockIdx.z * NC * NTOK + n;
#pragma unroll 3
    for (int c = 0; c < NC; c++) {
        float4 acc = sb[c];
#pragma unroll
        for (int i = 0; i < 36; i++) {
            float4 w = sw[i * NC + c];
            acc.x += w.x * f[i];
            acc.y += w.y * f[i];
            acc.z += w.z * f[i];
            acc.w += w.w * f[i];
        }
        outp[(size_t)c * NTOK] = acc;
    }
}

// ---------------------------------------------------------------------------
// Kernel 2: per-token attention (center query row only) + out_proj + fc_sa +
// residual + fc2 + layernorm.
// ---------------------------------------------------------------------------
__global__ void __launch_bounds__(256) attn_kernel(
    const float* __restrict__ hbase,   // residual input (z, NTOK, 32)
    float* __restrict__ obase,         // output (z, NTOK, 32)
    const float* __restrict__ opw, const float* __restrict__ opb,
    const float* __restrict__ saw, const float* __restrict__ sab,
    const float* __restrict__ f2w, const float* __restrict__ f2b,
    const float* __restrict__ lng, const float* __restrict__ lnb)
{
    __shared__ __align__(16) float s_opwT[34][36]; // [j][i] = opw[i][j], i-padded
    __shared__ __align__(16) float s_sawT[34][32]; // [i][k] = saw[k][i]
    __shared__ __align__(16) float s_f2wT[32][32]; // [i][k] = f2w[k][i]
    __shared__ float s_opb[36];
    __shared__ float s_sab[32], s_f2b[32], s_g[32], s_bb[32];

    int tid = threadIdx.x;
    for (int idx = tid; idx < 34 * 36; idx += 256) {
        int j = idx / 36, i = idx % 36;
        s_opwT[j][i] = (i < 34) ? opw[i * 34 + j] : 0.f;
    }
    for (int idx = tid; idx < 34 * 32; idx += 256) {
        int i = idx / 32, k = idx % 32;
        s_sawT[i][k] = saw[k * 34 + i];
    }
    for (int idx = tid; idx < 32 * 32; idx += 256) {
        int i = idx / 32, k = idx % 32;
        s_f2wT[i][k] = f2w[k * 32 + i];
    }
    if (tid < 36) s_opb[tid] = (tid < 34) ? opb[tid] : 0.f;
    if (tid < 32) {
        s_sab[tid] = sab[tid]; s_f2b[tid] = f2b[tid];
        s_g[tid] = lng[tid];   s_bb[tid] = lnb[tid];
    }
    __syncthreads();

    int n = blockIdx.x * 256 + tid;
    int p = n & 4095;
    int row = p >> 6, col = p & 63;
    // boundary-corrected neighborhood center
    int rs = row + (row == 0) - (row == 63);
    int cs = col + (col == 0) - (col == 63);
    int jb = (n >> 12) * 4096;

    const float4* S = g_scratch + (size_t)blockIdx.z * NC * NTOK;

    int jt[9];
#pragma unroll
    for (int s = 0; s < 9; s++) {
        int dr = s / 3 - 1, dc = s % 3 - 1;
        jt[s] = jb + (rs + dr) * 64 + (cs + dc);
    }

    // q = Q of center neighbor token jt[4]
    float4 q[9];
#pragma unroll
    for (int c = 0; c < 9; c++) q[c] = S[(size_t)c * NTOK + jt[4]];

    // scores (row 4 only)
    float sc[9];
#pragma unroll
    for (int s = 0; s < 9; s++) {
        const float4* kp = S + (size_t)9 * NTOK + jt[s];
        float a0 = 0.f, a1 = 0.f, a2 = 0.f, a3 = 0.f;
#pragma unroll
        for (int c = 0; c < 9; c++) {
            float4 k4 = kp[(size_t)c * NTOK];
            a0 += q[c].x * k4.x; a1 += q[c].y * k4.y;
            a2 += q[c].z * k4.z; a3 += q[c].w * k4.w;
        }
        sc[s] = (a0 + a1 + a2 + a3) * 0.17149858514250882f; // 1/sqrt(34)
    }

    // softmax over 9
    float m = sc[0];
#pragma unroll
    for (int s = 1; s < 9; s++) m = fmaxf(m, sc[s]);
    float sum = 0.f;
#pragma unroll
    for (int s = 0; s < 9; s++) { sc[s] = expf(sc[s] - m); sum += sc[s]; }
    float rinv = 1.f / sum;

    // av = sum_t w_t * V_t
    float4 av[9];
#pragma unroll
    for (int c = 0; c < 9; c++) { av[c].x = 0.f; av[c].y = 0.f; av[c].z = 0.f; av[c].w = 0.f; }
#pragma unroll
    for (int s = 0; s < 9; s++) {
        float wv = sc[s] * rinv;
        const float4* vp = S + (size_t)18 * NTOK + jt[s];
#pragma unroll
        for (int c = 0; c < 9; c++) {
            float4 v4 = vp[(size_t)c * NTOK];
            av[c].x += wv * v4.x; av[c].y += wv * v4.y;
            av[c].z += wv * v4.z; av[c].w += wv * v4.w;
        }
    }
    float avf[36];
#pragma unroll
    for (int c = 0; c < 9; c++) {
        avf[4 * c + 0] = av[c].x; avf[4 * c + 1] = av[c].y;
        avf[4 * c + 2] = av[c].z; avf[4 * c + 3] = av[c].w;
    }

    // out_proj: o = opw @ av + opb
    float o[36];
#pragma unroll
    for (int i = 0; i < 36; i++) o[i] = s_opb[i];
#pragma unroll
    for (int j = 0; j < 34; j++) {
        float a = avf[j];
        const float4* wr = reinterpret_cast<const float4*>(s_opwT[j]);
#pragma unroll
        for (int i4 = 0; i4 < 9; i4++) {
            float4 w = wr[i4];
            o[4 * i4 + 0] += w.x * a; o[4 * i4 + 1] += w.y * a;
            o[4 * i4 + 2] += w.z * a; o[4 * i4 + 3] += w.w * a;
        }
    }

    // fc_sa + residual: z = h + saw @ o + sab
    float z[32];
#pragma unroll
    for (int k = 0; k < 32; k++) z[k] = s_sab[k];
#pragma unroll
    for (int i = 0; i < 34; i++) {
        float a = o[i];
        const float4* wr = reinterpret_cast<const float4*>(s_sawT[i]);
#pragma unroll
        for (int k4 = 0; k4 < 8; k4++) {
            float4 w = wr[k4];
            z[4 * k4 + 0] += w.x * a; z[4 * k4 + 1] += w.y * a;
            z[4 * k4 + 2] += w.z * a; z[4 * k4 + 3] += w.w * a;
        }
    }
    const float* hrow = hbase + ((size_t)blockIdx.z * NTOK + n) * NH;
    const float4* h4 = reinterpret_cast<const float4*>(hrow);
#pragma unroll
    for (int k4 = 0; k4 < 8; k4++) {
        float4 hv = h4[k4];
        z[4 * k4 + 0] += hv.x; z[4 * k4 + 1] += hv.y;
        z[4 * k4 + 2] += hv.z; z[4 * k4 + 3] += hv.w;
    }

    // fc2: u = f2w @ z + f2b
    float u[32];
#pragma unroll
    for (int k = 0; k < 32; k++) u[k] = s_f2b[k];
#pragma unroll
    for (int i = 0; i < 32; i++) {
        float a = z[i];
        const float4* wr = reinterpret_cast<const float4*>(s_f2wT[i]);
#pragma unroll
        for (int k4 = 0; k4 < 8; k4++) {
            float4 w = wr[k4];
            u[4 * k4 + 0] += w.x * a; u[4 * k4 + 1] += w.y * a;
            u[4 * k4 + 2] += w.z * a; u[4 * k4 + 3] += w.w * a;
        }
    }

    // layernorm
    float mean = 0.f;
#pragma unroll
    for (int k = 0; k < 32; k++) mean += u[k];
    mean *= (1.f / 32.f);
    float var = 0.f;
#pragma unroll
    for (int k = 0; k < 32; k++) { float d = u[k] - mean; var += d * d; }
    var *= (1.f / 32.f);
    float r = rsqrtf(var + 1e-5f);

    float* orow = obase + ((size_t)blockIdx.z * NTOK + n) * NH;
    float4* o4 = reinterpret_cast<float4*>(orow);
#pragma unroll
    for (int k4 = 0; k4 < 8; k4++) {
        float4 y;
        y.x = (u[4 * k4 + 0] - mean) * r * s_g[4 * k4 + 0] + s_bb[4 * k4 + 0];
        y.y = (u[4 * k4 + 1] - mean) * r * s_g[4 * k4 + 1] + s_bb[4 * k4 + 1];
        y.z = (u[4 * k4 + 2] - mean) * r * s_g[4 * k4 + 2] + s_bb[4 * k4 + 2];
        y.w = (u[4 * k4 + 3] - mean) * r * s_g[4 * k4 + 3] + s_bb[4 * k4 + 3];
        o4[k4] = y;
    }
}

// ---------------------------------------------------------------------------
extern "C" void kernel_launch(void* const* d_in, const int* in_sizes, int n_in,
                              void* d_out, int out_size)
{
    const float* x   = (const float*)d_in[0];   // (10, 32768, 32)
    const float* ipw = (const float*)d_in[1];
    const float* ipb = (const float*)d_in[2];
    const float* opw = (const float*)d_in[3];
    const float* opb = (const float*)d_in[4];
    const float* saw = (const float*)d_in[5];
    const float* sab = (const float*)d_in[6];
    const float* f2w = (const float*)d_in[7];
    const float* f2b = (const float*)d_in[8];
    const float* lng = (const float*)d_in[9];
    const float* lnb = (const float*)d_in[10];
    float* out = (float*)d_out;                 // (60, 32768, 32)

    const int NB = NTOK / 256;                  // 128 blocks

    // Observation phase: 10 independent steps, batched over grid.z
    dim3 gobs(NB, 1, 10);
    qkv_kernel<<<gobs, 256>>>(x, ipw, ipb);
    attn_kernel<<<gobs, 256>>>(x, out, opw, opb, saw, sab, f2w, f2b, lng, lnb);

    // Prediction phase: 50 sequential steps rolling on the last output
    dim3 g1(NB, 1, 1);
    for (int i = 0; i < 50; i++) {
        const float* hprev = out + (size_t)(9 + i) * NTOK * NH;
        float* onext       = out + (size_t)(10 + i) * NTOK * NH;
        qkv_kernel<<<g1, 256>>>(hprev, ipw, ipb);
        attn_kernel<<<g1, 256>>>(hprev, onext, opw, opb, saw, sab, f2w, f2b, lng, lnb);
    }
}

// round 3
// speedup vs baseline: 1.1052x; 1.1052x over previous
#include <cuda_runtime.h>

#define NTOK 32768
#define NH 32
#define NC 27  // float4 chunks per token: Q=0..8, K=9..17, V=18..26 (each section 34 padded to 36)

// Scratch: 10 obs slices (pred reuses slice 0). 10*27*32768*16B = 141.6 MB
__device__ float4 g_scratch[10 * NC * NTOK];
// Folded fc_sa @ out_proj: CW (34x32 stored [j][k]) and cb (32)
__device__ float g_cw[34][32];
__device__ float g_cb[32];

// ---- f32x2 packed helpers --------------------------------------------------
typedef unsigned long long u64;

__device__ __forceinline__ u64 pack2(float lo, float hi) {
    u64 r; asm("mov.b64 %0, {%1, %2};" : "=l"(r) : "f"(lo), "f"(hi)); return r;
}
__device__ __forceinline__ void unpack2(u64 v, float& lo, float& hi) {
    asm("mov.b64 {%0, %1}, %2;" : "=f"(lo), "=f"(hi) : "l"(v));
}
__device__ __forceinline__ u64 ffma2(u64 a, u64 b, u64 c) {
    u64 d; asm("fma.rn.f32x2 %0, %1, %2, %3;" : "=l"(d) : "l"(a), "l"(b), "l"(c)); return d;
}
__device__ __forceinline__ u64 fadd2(u64 a, u64 b) {
    u64 d; asm("add.rn.f32x2 %0, %1, %2;" : "=l"(d) : "l"(a), "l"(b)); return d;
}

// ---------------------------------------------------------------------------
// Precompute kernel: CW[j][k] = sum_i saw[k][i] * opw[i][j]  (32x34)
//                    cb[k]    = sum_i saw[k][i] * opb[i] + sab[k]
// ---------------------------------------------------------------------------
__global__ void __launch_bounds__(128) precomp_kernel(
    const float* __restrict__ saw,  // (32, 34)
    const float* __restrict__ opw,  // (34, 34)
    const float* __restrict__ opb,  // (34)
    const float* __restrict__ sab)  // (32)
{
    int tid = threadIdx.x;
    for (int idx = tid; idx < 34 * 32; idx += 128) {
        int j = idx / 32, k = idx % 32;
        float acc = 0.f;
#pragma unroll
        for (int i = 0; i < 34; i++) acc += saw[k * 34 + i] * opw[i * 34 + j];
        g_cw[j][k] = acc;
    }
    if (tid < 32) {
        float acc = sab[tid];
#pragma unroll
        for (int i = 0; i < 34; i++) acc += saw[tid * 34 + i] * opb[i];
        g_cb[tid] = acc;
    }
}

// ---------------------------------------------------------------------------
// Kernel 1: per-token QKV projection (packed f32x2).
//   f = [h(n,0:32), row/64, col/64, 0, 0]
//   chunk c: section sec=c/9 (Q/K/V), within-offset ww=4*(c%9)
// ---------------------------------------------------------------------------
__global__ void __launch_bounds__(128) qkv_kernel(
    const float* __restrict__ hbase,   // (z, NTOK, 32)
    const float* __restrict__ ipw,     // (102, 34)
    const float* __restrict__ ipb)     // (102)
{
    __shared__ __align__(16) float4 sw[36 * NC];  // sw[i*NC + c]
    __shared__ __align__(16) float4 sb[NC];

    int tid = threadIdx.x;
    for (int idx = tid; idx < 36 * NC; idx += 128) {
        int i = idx / NC, c = idx % NC;
        int sec = c / 9, ww = 4 * (c % 9);
        float4 v;
        v.x = (i < 34 && ww + 0 < 34) ? ipw[(sec * 34 + ww + 0) * 34 + i] : 0.f;
        v.y = (i < 34 && ww + 1 < 34) ? ipw[(sec * 34 + ww + 1) * 34 + i] : 0.f;
        v.z = (i < 34 && ww + 2 < 34) ? ipw[(sec * 34 + ww + 2) * 34 + i] : 0.f;
        v.w = (i < 34 && ww + 3 < 34) ? ipw[(sec * 34 + ww + 3) * 34 + i] : 0.f;
        sw[idx] = v;
    }
    if (tid < NC) {
        int sec = tid / 9, ww = 4 * (tid % 9);
        float4 v;
        v.x = (ww + 0 < 34) ? ipb[sec * 34 + ww + 0] : 0.f;
        v.y = (ww + 1 < 34) ? ipb[sec * 34 + ww + 1] : 0.f;
        v.z = (ww + 2 < 34) ? ipb[sec * 34 + ww + 2] : 0.f;
        v.w = (ww + 3 < 34) ? ipb[sec * 34 + ww + 3] : 0.f;
        sb[tid] = v;
    }
    __syncthreads();

    int n = blockIdx.x * 128 + tid;
    const float4* h4 = reinterpret_cast<const float4*>(
        hbase + ((size_t)blockIdx.z * NTOK + n) * NH);

    float f[36];
#pragma unroll
    for (int i = 0; i < 8; i++) {
        float4 v = h4[i];
        f[4 * i + 0] = v.x; f[4 * i + 1] = v.y;
        f[4 * i + 2] = v.z; f[4 * i + 3] = v.w;
    }
    int p = n & 4095;
    f[32] = (float)(p >> 6) * (1.f / 64.f);
    f[33] = (float)(p & 63) * (1.f / 64.f);
    f[34] = 0.f; f[35] = 0.f;

    float4* outp = g_scratch + (size_t)blockIdx.z * NC * NTOK + n;

    // 3 groups of 9 chunks: acc = 18 packed u64 per group
#pragma unroll
    for (int g = 0; g < 3; g++) {
        u64 acc[18];
#pragma unroll
        for (int c8 = 0; c8 < 9; c8++) {
            const ulonglong2* b2 = reinterpret_cast<const ulonglong2*>(&sb[g * 9 + c8]);
            ulonglong2 bv = *b2;
            acc[2 * c8 + 0] = bv.x;
            acc[2 * c8 + 1] = bv.y;
        }
#pragma unroll
        for (int i = 0; i < 36; i++) {
            u64 fp = pack2(f[i], f[i]);
#pragma unroll
            for (int c8 = 0; c8 < 9; c8++) {
                ulonglong2 w = *reinterpret_cast<const ulonglong2*>(&sw[i * NC + g * 9 + c8]);
                acc[2 * c8 + 0] = ffma2(w.x, fp, acc[2 * c8 + 0]);
                acc[2 * c8 + 1] = ffma2(w.y, fp, acc[2 * c8 + 1]);
            }
        }
#pragma unroll
        for (int c8 = 0; c8 < 9; c8++) {
            ulonglong2 o2;
            o2.x = acc[2 * c8 + 0];
            o2.y = acc[2 * c8 + 1];
            outp[(size_t)(g * 9 + c8) * NTOK] = *reinterpret_cast<float4*>(&o2);
        }
    }
}

// ---------------------------------------------------------------------------
// Kernel 2: attention (center query row) + folded (fc_sa@out_proj) + residual
// + fc2 + layernorm, packed f32x2 throughout.
// ---------------------------------------------------------------------------
__global__ void __launch_bounds__(128) attn_kernel(
    const float* __restrict__ hbase,   // residual input (z, NTOK, 32)
    float* __restrict__ obase,         // output (z, NTOK, 32)
    const float* __restrict__ f2w, const float* __restrict__ f2b,
    const float* __restrict__ lng, const float* __restrict__ lnb)
{
    __shared__ __align__(16) float s_cw[34][32];   // [j][k] = CW[j][k]
    __shared__ __align__(16) float s_f2[32][32];   // [i][k] = f2w[k][i]
    __shared__ __align__(16) float s_cb[32];
    __shared__ __align__(16) float s_f2b[32];
    __shared__ float s_g[32], s_bb[32];

    int tid = threadIdx.x;
    for (int idx = tid; idx < 34 * 32; idx += 128)
        s_cw[idx / 32][idx % 32] = g_cw[idx / 32][idx % 32];
    for (int idx = tid; idx < 32 * 32; idx += 128) {
        int i = idx / 32, k = idx % 32;
        s_f2[i][k] = f2w[k * 32 + i];
    }
    if (tid < 32) {
        s_cb[tid] = g_cb[tid]; s_f2b[tid] = f2b[tid];
        s_g[tid] = lng[tid];   s_bb[tid] = lnb[tid];
    }
    __syncthreads();

    int n = blockIdx.x * 128 + tid;
    int p = n & 4095;
    int row = p >> 6, col = p & 63;
    int rs = row + (row == 0) - (row == 63);
    int cs = col + (col == 0) - (col == 63);
    int jb = (n >> 12) * 4096;

    const float4* S = g_scratch + (size_t)blockIdx.z * NC * NTOK;

    int jt[9];
#pragma unroll
    for (int s = 0; s < 9; s++) {
        int dr = s / 3 - 1, dc = s % 3 - 1;
        jt[s] = jb + (rs + dr) * 64 + (cs + dc);
    }

    // q = Q of center neighbor token jt[4], packed pairs
    u64 qp[18];
#pragma unroll
    for (int c = 0; c < 9; c++) {
        ulonglong2 qv = *reinterpret_cast<const ulonglong2*>(&S[(size_t)c * NTOK + jt[4]]);
        qp[2 * c] = qv.x; qp[2 * c + 1] = qv.y;
    }

    // scores (row 4 only)
    float sc[9];
#pragma unroll
    for (int s = 0; s < 9; s++) {
        const float4* kp = S + (size_t)9 * NTOK + jt[s];
        u64 a0 = 0ull, a1 = 0ull;
#pragma unroll
        for (int c = 0; c < 9; c++) {
            ulonglong2 kv = *reinterpret_cast<const ulonglong2*>(&kp[(size_t)c * NTOK]);
            a0 = ffma2(qp[2 * c], kv.x, a0);
            a1 = ffma2(qp[2 * c + 1], kv.y, a1);
        }
        float x0, x1, x2, x3;
        unpack2(a0, x0, x1); unpack2(a1, x2, x3);
        sc[s] = (x0 + x1 + x2 + x3) * 0.17149858514250882f; // 1/sqrt(34)
    }

    // softmax over 9
    float m = sc[0];
#pragma unroll
    for (int s = 1; s < 9; s++) m = fmaxf(m, sc[s]);
    float sum = 0.f;
#pragma unroll
    for (int s = 0; s < 9; s++) { sc[s] = __expf(sc[s] - m); sum += sc[s]; }
    float rinv = 1.f / sum;

    // av = sum_t w_t * V_t (packed)
    u64 avp[18];
#pragma unroll
    for (int c = 0; c < 18; c++) avp[c] = 0ull;
#pragma unroll
    for (int s = 0; s < 9; s++) {
        float wv = sc[s] * rinv;
        u64 wvp = pack2(wv, wv);
        const float4* vp = S + (size_t)18 * NTOK + jt[s];
#pragma unroll
        for (int c = 0; c < 9; c++) {
            ulonglong2 vv = *reinterpret_cast<const ulonglong2*>(&vp[(size_t)c * NTOK]);
            avp[2 * c]     = ffma2(wvp, vv.x, avp[2 * c]);
            avp[2 * c + 1] = ffma2(wvp, vv.y, avp[2 * c + 1]);
        }
    }
    float avf[36];
#pragma unroll
    for (int c = 0; c < 18; c++) unpack2(avp[c], avf[2 * c], avf[2 * c + 1]);

    // z = h + CW @ av + cb   (16 packed accumulators = 32 outputs)
    u64 z[16];
#pragma unroll
    for (int k = 0; k < 16; k++) z[k] = *reinterpret_cast<const u64*>(&s_cb[2 * k]);
    {
        const float4* h4 = reinterpret_cast<const float4*>(
            hbase + ((size_t)blockIdx.z * NTOK + n) * NH);
#pragma unroll
        for (int q4 = 0; q4 < 8; q4++) {
            ulonglong2 hv = *reinterpret_cast<const ulonglong2*>(&h4[q4]);
            z[2 * q4]     = fadd2(z[2 * q4], hv.x);
            z[2 * q4 + 1] = fadd2(z[2 * q4 + 1], hv.y);
        }
    }
#pragma unroll
    for (int j = 0; j < 34; j++) {
        u64 ap = pack2(avf[j], avf[j]);
#pragma unroll
        for (int k = 0; k < 16; k++)
            z[k] = ffma2(ap, *reinterpret_cast<const u64*>(&s_cw[j][2 * k]), z[k]);
    }
    float zf[32];
#pragma unroll
    for (int k = 0; k < 16; k++) unpack2(z[k], zf[2 * k], zf[2 * k + 1]);

    // u = f2w @ z + f2b
    u64 u[16];
#pragma unroll
    for (int k = 0; k < 16; k++) u[k] = *reinterpret_cast<const u64*>(&s_f2b[2 * k]);
#pragma unroll
    for (int i = 0; i < 32; i++) {
        u64 ap = pack2(zf[i], zf[i]);
#pragma unroll
        for (int k = 0; k < 16; k++)
            u[k] = ffma2(ap, *reinterpret_cast<const u64*>(&s_f2[i][2 * k]), u[k]);
    }
    float uf[32];
#pragma unroll
    for (int k = 0; k < 16; k++) unpack2(u[k], uf[2 * k], uf[2 * k + 1]);

    // layernorm
    float mean = 0.f;
#pragma unroll
    for (int k = 0; k < 32; k++) mean += uf[k];
    mean *= (1.f / 32.f);
    float var = 0.f;
#pragma unroll
    for (int k = 0; k < 32; k++) { float d = uf[k] - mean; var += d * d; }
    var *= (1.f / 32.f);
    float r = rsqrtf(var + 1e-5f);

    float4* o4 = reinterpret_cast<float4*>(
        obase + ((size_t)blockIdx.z * NTOK + n) * NH);
#pragma unroll
    for (int k4 = 0; k4 < 8; k4++) {
        float4 y;
        y.x = (uf[4 * k4 + 0] - mean) * r * s_g[4 * k4 + 0] + s_bb[4 * k4 + 0];
        y.y = (uf[4 * k4 + 1] - mean) * r * s_g[4 * k4 + 1] + s_bb[4 * k4 + 1];
        y.z = (uf[4 * k4 + 2] - mean) * r * s_g[4 * k4 + 2] + s_bb[4 * k4 + 2];
        y.w = (uf[4 * k4 + 3] - mean) * r * s_g[4 * k4 + 3] + s_bb[4 * k4 + 3];
        o4[k4] = y;
    }
}

// ---------------------------------------------------------------------------
extern "C" void kernel_launch(void* const* d_in, const int* in_sizes, int n_in,
                              void* d_out, int out_size)
{
    const float* x   = (const float*)d_in[0];   // (10, 32768, 32)
    const float* ipw = (const float*)d_in[1];
    const float* ipb = (const float*)d_in[2];
    const float* opw = (const float*)d_in[3];
    const float* opb = (const float*)d_in[4];
    const float* saw = (const float*)d_in[5];
    const float* sab = (const float*)d_in[6];
    const float* f2w = (const float*)d_in[7];
    const float* f2b = (const float*)d_in[8];
    const float* lng = (const float*)d_in[9];
    const float* lnb = (const float*)d_in[10];
    float* out = (float*)d_out;                 // (60, 32768, 32)

    const int NB = NTOK / 128;                  // 256 blocks

    precomp_kernel<<<1, 128>>>(saw, opw, opb, sab);

    // Observation phase: 10 independent steps, batched over grid.z
    dim3 gobs(NB, 1, 10);
    qkv_kernel<<<gobs, 128>>>(x, ipw, ipb);
    attn_kernel<<<gobs, 128>>>(x, out, f2w, f2b, lng, lnb);

    // Prediction phase: 50 sequential steps rolling on the last output
    dim3 g1(NB, 1, 1);
    for (int i = 0; i < 50; i++) {
        const float* hprev = out + (size_t)(9 + i) * NTOK * NH;
        float* onext       = out + (size_t)(10 + i) * NTOK * NH;
        qkv_kernel<<<g1, 128>>>(hprev, ipw, ipb);
        attn_kernel<<<g1, 128>>>(hprev, onext, f2w, f2b, lng, lnb);
    }
}